// round 4
// baseline (speedup 1.0000x reference)
#include <cuda_runtime.h>
#include <cuda_bf16.h>
#include <math.h>

#define NP 64
#define NR 8
#define NK 500
#define H 256
#define HEADS 8
#define VD 8
#define HD 32
#define BB (NP*NR)          // 512
#define NEGINF (__int_as_float(0xff800000))

// ---------------- scratch (device globals; no allocations allowed) ----------------
__device__ float g_gates[BB * 4 * H];     // 512 x 1024
__device__ float g_xcat [BB * H];         // 512 x 256
__device__ float g_qm   [BB * H];         // 512 x 256
__device__ float g_logit[BB * NK];        // 512 x 500

__device__ __forceinline__ float tanha(float x) {
    float y; asm("tanh.approx.f32 %0, %1;" : "=f"(y) : "f"(x)); return y;
}
__device__ __forceinline__ float sigm(float x) { return 1.0f / (1.0f + expf(-x)); }

// =====================================================================
// Kernel 1: gates = query @ W_ih^T + state1 @ W_hh^T + b_ih + b_hh
// C[512,1024], K=512 (256 query + 256 state1). 64x64 tiles, 4x4 micro.
// =====================================================================
__global__ __launch_bounds__(256)
void k_gates(const float* __restrict__ q, const float* __restrict__ s1,
             const float* __restrict__ Wih, const float* __restrict__ Whh,
             const float* __restrict__ bih, const float* __restrict__ bhh)
{
    __shared__ float As[16][68];
    __shared__ float Bs[16][68];
    const int t  = threadIdx.x;
    const int tx = t & 15, ty = t >> 4;
    const int n0 = blockIdx.x * 64;
    const int m0 = blockIdx.y * 64;

    float acc[4][4] = {};

    for (int kt = 0; kt < 512; kt += 16) {
        const float* Ap; const float* Wp; int kk;
        if (kt < 256) { Ap = q;  Wp = Wih; kk = kt; }
        else          { Ap = s1; Wp = Whh; kk = kt - 256; }
        #pragma unroll
        for (int r = 0; r < 4; r++) {
            int i = r * 256 + t;           // 0..1023
            int mm = i >> 4, kx = i & 15;  // 64 rows x 16 k
            As[kx][mm] = Ap[(m0 + mm) * 256 + kk + kx];
            Bs[kx][mm] = Wp[(n0 + mm) * 256 + kk + kx];
        }
        __syncthreads();
        #pragma unroll
        for (int k = 0; k < 16; k++) {
            float4 a4 = *(const float4*)&As[k][ty * 4];
            float4 b4 = *(const float4*)&Bs[k][tx * 4];
            float av[4] = {a4.x, a4.y, a4.z, a4.w};
            float bv[4] = {b4.x, b4.y, b4.z, b4.w};
            #pragma unroll
            for (int r = 0; r < 4; r++)
                #pragma unroll
                for (int c = 0; c < 4; c++)
                    acc[r][c] = fmaf(av[r], bv[c], acc[r][c]);
        }
        __syncthreads();
    }
    #pragma unroll
    for (int r = 0; r < 4; r++) {
        int m = m0 + ty * 4 + r;
        #pragma unroll
        for (int c = 0; c < 4; c++) {
            int n = n0 + tx * 4 + c;
            g_gates[m * 1024 + n] = acc[r][c] + bih[n] + bhh[n];
        }
    }
}

// =====================================================================
// Kernel 2: LSTM activations -> h, c  (written straight into d_out)
// =====================================================================
__global__ __launch_bounds__(256)
void k_act(const float* __restrict__ s2, float* __restrict__ out)
{
    int idx = blockIdx.x * 256 + threadIdx.x;   // 0..131071
    int b = idx >> 8, j = idx & 255;
    const float* g = g_gates + b * 1024;
    float gi = g[j], gf = g[j + 256], gg = g[j + 512], go = g[j + 768];
    float c = sigm(gf) * s2[idx] + sigm(gi) * tanhf(gg);
    float h = sigm(go) * tanhf(c);
    out[idx] = h;
    out[BB * H + idx] = c;
}

// =====================================================================
// Kernel 3: per-(p, head) multi-head attention glimpse.
// Produces x_cat[p][q][a*32+d].
// =====================================================================
struct SmemAttn {
    float hs_x[8][8][32];   // phase0/1: h rows [8][256]; later: xpart[w][q][d]
    float Qs[8][32];
    float Ss[8][512];
    float4 Vs[128 * 8];     // 128 rows x 32 floats
};

__global__ __launch_bounds__(256)
void k_attn(const float* __restrict__ K, const float* __restrict__ V,
            const float* __restrict__ nnQ, const int* __restrict__ mask,
            const float* __restrict__ hbuf)
{
    __shared__ SmemAttn sm;
    const int p = blockIdx.x, a = blockIdx.y;
    const int t = threadIdx.x, w = t >> 5, l = t & 31;
    float* hs = (float*)sm.hs_x;   // [8][256] flattened

    // load h rows for the 8 rollouts of problem p
    for (int i = t; i < 2048; i += 256) hs[i] = hbuf[p * 2048 + i];
    __syncthreads();

    // Q[q][d] = sum_h h[q][h] * nnQ[a][h][d], scaled by 1/sqrt(HD)
    {
        int q = t >> 5, d = t & 31;
        const float* qp = nnQ + a * (H * HD) + d;
        float s = 0.f;
        for (int hh = 0; hh < H; hh++) s = fmaf(hs[q * H + hh], qp[hh * HD], s);
        sm.Qs[q][d] = s * 0.17677669529663687f;
    }
    __syncthreads();

    // scores: each thread owns one k, computes all 8 q dots (K row in regs)
    const float* Kp = K + (size_t)(a * NP + p) * NK * HD;
    for (int sweep = 0; sweep < 2; sweep++) {
        int k = sweep * 256 + t;
        if (k < NK) {
            float4 kr[8];
            const float4* kp4 = (const float4*)(Kp + k * HD);
            #pragma unroll
            for (int i = 0; i < 8; i++) kr[i] = kp4[i];
            #pragma unroll
            for (int q = 0; q < 8; q++) {
                const float4* q4 = (const float4*)sm.Qs[q];
                float acc = 0.f;
                #pragma unroll
                for (int i = 0; i < 8; i++) {
                    float4 qq = q4[i];
                    acc = fmaf(kr[i].x, qq.x, acc);
                    acc = fmaf(kr[i].y, qq.y, acc);
                    acc = fmaf(kr[i].z, qq.z, acc);
                    acc = fmaf(kr[i].w, qq.w, acc);
                }
                int m = mask[(p * NR + q) * NK + k];
                sm.Ss[q][k] = m ? NEGINF : acc;
            }
        }
    }
    __syncthreads();

    // softmax: warp w handles row q=w
    {
        float mx = NEGINF;
        for (int k = l; k < NK; k += 32) mx = fmaxf(mx, sm.Ss[w][k]);
        #pragma unroll
        for (int o = 16; o; o >>= 1) mx = fmaxf(mx, __shfl_xor_sync(~0u, mx, o));
        float sum = 0.f;
        for (int k = l; k < NK; k += 32) {
            float e = __expf(sm.Ss[w][k] - mx);
            sm.Ss[w][k] = e; sum += e;
        }
        #pragma unroll
        for (int o = 16; o; o >>= 1) sum += __shfl_xor_sync(~0u, sum, o);
        float inv = 1.f / sum;
        for (int k = l; k < NK; k += 32) sm.Ss[w][k] *= inv;
    }
    __syncthreads();

    // x[q][d] = sum_k S[q][k] * V[k][d] ; V streamed through shared in chunks.
    // lane: q = l>>2 (8 q), dq = l&3 (each lane owns 8 d's) -> smem broadcast over q.
    const float4* Vp4 = (const float4*)(V + (size_t)(a * NP + p) * NK * HD);
    int q = l >> 2, dq = l & 3;
    float acc8[8] = {};
    for (int c0 = 0; c0 < NK; c0 += 128) {
        int clen = min(128, NK - c0);
        for (int i = t; i < clen * 8; i += 256) sm.Vs[i] = Vp4[c0 * 8 + i];
        __syncthreads();
        for (int kk = w; kk < clen; kk += 8) {
            float sv = sm.Ss[q][c0 + kk];
            float4 v0 = sm.Vs[kk * 8 + dq * 2];
            float4 v1 = sm.Vs[kk * 8 + dq * 2 + 1];
            acc8[0] = fmaf(sv, v0.x, acc8[0]);
            acc8[1] = fmaf(sv, v0.y, acc8[1]);
            acc8[2] = fmaf(sv, v0.z, acc8[2]);
            acc8[3] = fmaf(sv, v0.w, acc8[3]);
            acc8[4] = fmaf(sv, v1.x, acc8[4]);
            acc8[5] = fmaf(sv, v1.y, acc8[5]);
            acc8[6] = fmaf(sv, v1.z, acc8[6]);
            acc8[7] = fmaf(sv, v1.w, acc8[7]);
        }
        __syncthreads();
    }
    #pragma unroll
    for (int i = 0; i < 8; i++) sm.hs_x[w][q][dq * 8 + i] = acc8[i];
    __syncthreads();
    {
        int q2 = t >> 5, d2 = t & 31;
        float s = 0.f;
        #pragma unroll
        for (int ww = 0; ww < 8; ww++) s += sm.hs_x[ww][q2][d2];
        g_xcat[(p * NR + q2) * H + a * HD + d2] = s;
    }
}

// =====================================================================
// Kernel 4: qm = x_cat @ nn_O   (512x256 @ 256x256)
// block = 4 rows, 256 threads = one output column each
// =====================================================================
__global__ __launch_bounds__(256)
void k_qm(const float* __restrict__ nnO)
{
    __shared__ float xs[4][256];
    const int r0 = blockIdx.x * 4;
    const int t = threadIdx.x;
    for (int i = t; i < 1024; i += 256) xs[i >> 8][i & 255] = g_xcat[r0 * 256 + i];
    __syncthreads();
    float acc[4] = {};
    for (int k = 0; k < 256; k++) {
        float wv = nnO[k * 256 + t];
        #pragma unroll
        for (int r = 0; r < 4; r++) acc[r] = fmaf(xs[r][k], wv, acc[r]);
    }
    #pragma unroll
    for (int r = 0; r < 4; r++) g_qm[(r0 + r) * 256 + t] = acc[r];
}

// =====================================================================
// Kernel 5: logits. block = (p, ktile of 64). warp owns one k per iter.
// logit[p][q][k] = sum_h tanh(X + vf + qm) * W  (vf fused on the fly)
// =====================================================================
__global__ __launch_bounds__(256)
void k_logit(const float* __restrict__ X, const float* __restrict__ varfeat,
             const float* __restrict__ nnA, const float* __restrict__ nnB,
             const float* __restrict__ nnW, const int* __restrict__ mask)
{
    __shared__ float qs[8][256];
    const int p = blockIdx.y, kt = blockIdx.x;
    const int t = threadIdx.x, w = t >> 5, l = t & 31;
    for (int i = t; i < 2048; i += 256) qs[i >> 8][i & 255] = g_qm[p * 2048 + i];

    float Ar[8][8], Wr[8], Br[8];
    #pragma unroll
    for (int i = 0; i < 8; i++) {
        int hh = l + 32 * i;
        Wr[i] = nnW[hh];
        Br[i] = nnB[hh];
        #pragma unroll
        for (int v = 0; v < 8; v++) Ar[v][i] = nnA[v * 256 + hh];
    }
    __syncthreads();

    for (int it = 0; it < 8; it++) {
        int k = kt * 64 + it * 8 + w;
        if (k >= NK) continue;
        float vv[8];
        #pragma unroll
        for (int v = 0; v < 8; v++) vv[v] = __ldg(&varfeat[(p * VD + v) * NK + k]);
        const float* Xp = X + ((size_t)p * NK + k) * H;
        float base[8];
        #pragma unroll
        for (int i = 0; i < 8; i++) {
            float b = Xp[l + 32 * i] + Br[i];
            #pragma unroll
            for (int v = 0; v < 8; v++) b = fmaf(vv[v], Ar[v][i], b);
            base[i] = b;
        }
        #pragma unroll
        for (int q = 0; q < 8; q++) {
            float acc = 0.f;
            #pragma unroll
            for (int i = 0; i < 8; i++) {
                float tt = tanha(base[i] + qs[q][l + 32 * i]);
                acc = fmaf(tt, Wr[i], acc);
            }
            #pragma unroll
            for (int o = 16; o; o >>= 1) acc += __shfl_xor_sync(~0u, acc, o);
            if (l == 0) {
                int m = mask[(p * NR + q) * NK + k];
                g_logit[(p * NR + q) * NK + k] = m ? NEGINF : acc;
            }
        }
    }
}

// =====================================================================
// Kernel 6: greedy choose + log_softmax at chosen index. block per row b.
// =====================================================================
__global__ __launch_bounds__(256)
void k_choose(float* __restrict__ out)
{
    __shared__ float ls[NK];
    __shared__ float rv[256];
    __shared__ int   ri[256];
    __shared__ float rs[256];
    const int b = blockIdx.x;
    const int t = threadIdx.x;

    float lm = NEGINF; int li = 0x7fffffff;
    for (int k = t; k < NK; k += 256) {
        float lg = g_logit[b * NK + k];
        float l  = (lg == NEGINF) ? NEGINF : tanhf(lg) * 10.0f;
        ls[k] = l;
        if (l > lm || (l == lm && k < li)) { lm = l; li = k; }
    }
    rv[t] = lm; ri[t] = li;
    __syncthreads();
    for (int s = 128; s; s >>= 1) {
        if (t < s) {
            float v2 = rv[t + s]; int i2 = ri[t + s];
            if (v2 > rv[t] || (v2 == rv[t] && i2 < ri[t])) { rv[t] = v2; ri[t] = i2; }
        }
        __syncthreads();
    }
    float maxv = rv[0]; int chosen = ri[0];

    float psum = 0.f;
    for (int k = t; k < NK; k += 256) psum += expf(ls[k] - maxv);
    rs[t] = psum;
    __syncthreads();
    for (int s = 128; s; s >>= 1) {
        if (t < s) rs[t] += rs[t + s];
        __syncthreads();
    }
    if (t == 0) out[2 * BB * H + b] = ls[chosen] - maxv - logf(rs[0]);
}

// =====================================================================
// launch
// =====================================================================
extern "C" void kernel_launch(void* const* d_in, const int* in_sizes, int n_in,
                              void* d_out, int out_size)
{
    const float* X       = (const float*)d_in[0];
    const float* K       = (const float*)d_in[1];
    const float* V       = (const float*)d_in[2];
    const float* query   = (const float*)d_in[3];
    const float* state1  = (const float*)d_in[4];
    const float* state2  = (const float*)d_in[5];
    const float* varfeat = (const float*)d_in[6];
    const int*   mask    = (const int*)  d_in[7];
    const float* nnQ     = (const float*)d_in[8];
    const float* nnO     = (const float*)d_in[9];
    const float* nnA     = (const float*)d_in[10];
    const float* nnB     = (const float*)d_in[11];
    const float* nnW     = (const float*)d_in[12];
    const float* Wih     = (const float*)d_in[13];
    const float* Whh     = (const float*)d_in[14];
    const float* bih     = (const float*)d_in[15];
    const float* bhh     = (const float*)d_in[16];
    float* out = (float*)d_out;

    k_gates <<<dim3(16, 8), 256>>>(query, state1, Wih, Whh, bih, bhh);
    k_act   <<<512, 256>>>(state2, out);
    k_attn  <<<dim3(NP, HEADS), 256>>>(K, V, nnQ, mask, out);
    k_qm    <<<128, 256>>>(nnO);
    k_logit <<<dim3(8, NP), 256>>>(X, varfeat, nnA, nnB, nnW, mask);
    k_choose<<<BB, 256>>>(out);
}

// round 5
// speedup vs baseline: 1.0431x; 1.0431x over previous
#include <cuda_runtime.h>
#include <cuda_bf16.h>
#include <math.h>

#define NP 64
#define NR 8
#define NK 500
#define H 256
#define HEADS 8
#define VD 8
#define HD 32
#define BB (NP*NR)          // 512
#define NEGINF (__int_as_float(0xff800000))

// ---------------- scratch (device globals; no allocations allowed) ----------------
__device__ float g_gates[BB * 4 * H];     // 512 x 1024
__device__ float g_xcat [BB * H];         // 512 x 256
__device__ float g_qm   [BB * H];         // 512 x 256
__device__ float g_logit[BB * NK];        // 512 x 500

__device__ __forceinline__ float tanha(float x) {
    float y; asm("tanh.approx.f32 %0, %1;" : "=f"(y) : "f"(x)); return y;
}
__device__ __forceinline__ float sigm(float x) { return 1.0f / (1.0f + __expf(-x)); }

// =====================================================================
// Kernel 1: gates = query @ W_ih^T + state1 @ W_hh^T + b_ih + b_hh
// C[512,1024], K=512. 64x64 tiles, 4x4 micro, double-buffered smem.
// =====================================================================
__global__ __launch_bounds__(256)
void k_gates(const float* __restrict__ q, const float* __restrict__ s1,
             const float* __restrict__ Wih, const float* __restrict__ Whh,
             const float* __restrict__ bih, const float* __restrict__ bhh)
{
    __shared__ float As[2][16][68];
    __shared__ float Bs[2][16][68];
    const int t  = threadIdx.x;
    const int tx = t & 15, ty = t >> 4;
    const int n0 = blockIdx.x * 64;
    const int m0 = blockIdx.y * 64;

    float acc[4][4] = {};

    auto fetch = [&](int kt, int r, float& a, float& b) {
        int i = r * 256 + t;
        int mm = i >> 4, kx = i & 15;
        int kk = kt * 16;
        const float* Ap = (kk < 256) ? q   : s1;
        const float* Wp = (kk < 256) ? Wih : Whh;
        int k2 = kk & 255;
        a = Ap[(m0 + mm) * 256 + k2 + kx];
        b = Wp[(n0 + mm) * 256 + k2 + kx];
    };

    // preload tile 0
    #pragma unroll
    for (int r = 0; r < 4; r++) {
        float a, b; fetch(0, r, a, b);
        int i = r * 256 + t; int mm = i >> 4, kx = i & 15;
        As[0][kx][mm] = a; Bs[0][kx][mm] = b;
    }
    __syncthreads();

    int cur = 0;
    for (int kt = 0; kt < 32; kt++) {
        float pa[4], pb[4];
        if (kt < 31) {
            #pragma unroll
            for (int r = 0; r < 4; r++) fetch(kt + 1, r, pa[r], pb[r]);
        }
        #pragma unroll
        for (int k = 0; k < 16; k++) {
            float4 a4 = *(const float4*)&As[cur][k][ty * 4];
            float4 b4 = *(const float4*)&Bs[cur][k][tx * 4];
            float av[4] = {a4.x, a4.y, a4.z, a4.w};
            float bv[4] = {b4.x, b4.y, b4.z, b4.w};
            #pragma unroll
            for (int r = 0; r < 4; r++)
                #pragma unroll
                for (int c = 0; c < 4; c++)
                    acc[r][c] = fmaf(av[r], bv[c], acc[r][c]);
        }
        if (kt < 31) {
            int nxt = cur ^ 1;
            #pragma unroll
            for (int r = 0; r < 4; r++) {
                int i = r * 256 + t; int mm = i >> 4, kx = i & 15;
                As[nxt][kx][mm] = pa[r]; Bs[nxt][kx][mm] = pb[r];
            }
            __syncthreads();
            cur = nxt;
        }
    }
    #pragma unroll
    for (int r = 0; r < 4; r++) {
        int m = m0 + ty * 4 + r;
        #pragma unroll
        for (int c = 0; c < 4; c++) {
            int n = n0 + tx * 4 + c;
            g_gates[m * 1024 + n] = acc[r][c] + bih[n] + bhh[n];
        }
    }
}

// =====================================================================
// Kernel 2: LSTM activations -> h, c  (written straight into d_out)
// =====================================================================
__global__ __launch_bounds__(256)
void k_act(const float* __restrict__ s2, float* __restrict__ out)
{
    int idx = blockIdx.x * 256 + threadIdx.x;   // 0..131071
    int b = idx >> 8, j = idx & 255;
    const float* g = g_gates + b * 1024;
    float gi = g[j], gf = g[j + 256], gg = g[j + 512], go = g[j + 768];
    float c = sigm(gf) * s2[idx] + sigm(gi) * tanhf(gg);
    float h = sigm(go) * tanhf(c);
    out[idx] = h;
    out[BB * H + idx] = c;
}

// =====================================================================
// Kernel 3: per-(p, head) multi-head attention glimpse.
// Produces x_cat[p][q][a*32+d].
// =====================================================================
struct SmemAttn {
    float hs_x[8][8][32];   // phase0/1: h rows [8][256]; later: xpart[w][q][d]
    float Qs[8][32];
    float Ss[8][512];
    float4 Vs[128 * 8];     // 128 rows x 32 floats
};

__global__ __launch_bounds__(256)
void k_attn(const float* __restrict__ K, const float* __restrict__ V,
            const float* __restrict__ nnQ, const int* __restrict__ mask,
            const float* __restrict__ hbuf)
{
    __shared__ SmemAttn sm;
    const int p = blockIdx.x, a = blockIdx.y;
    const int t = threadIdx.x, w = t >> 5, l = t & 31;
    float* hs = (float*)sm.hs_x;   // [8][256] flattened

    // load h rows for the 8 rollouts of problem p
    for (int i = t; i < 2048; i += 256) hs[i] = hbuf[p * 2048 + i];
    __syncthreads();

    // Q[q][d] = sum_h h[q][h] * nnQ[a][h][d], scaled by 1/sqrt(HD)
    {
        int q = t >> 5, d = t & 31;
        const float* qp = nnQ + a * (H * HD) + d;
        float s = 0.f;
        for (int hh = 0; hh < H; hh++) s = fmaf(hs[q * H + hh], qp[hh * HD], s);
        sm.Qs[q][d] = s * 0.17677669529663687f;
    }
    __syncthreads();

    // scores: each thread owns one k, computes all 8 q dots (K row in regs)
    const float* Kp = K + (size_t)(a * NP + p) * NK * HD;
    for (int sweep = 0; sweep < 2; sweep++) {
        int k = sweep * 256 + t;
        if (k < NK) {
            float4 kr[8];
            const float4* kp4 = (const float4*)(Kp + k * HD);
            #pragma unroll
            for (int i = 0; i < 8; i++) kr[i] = kp4[i];
            #pragma unroll
            for (int q = 0; q < 8; q++) {
                const float4* q4 = (const float4*)sm.Qs[q];
                float acc = 0.f;
                #pragma unroll
                for (int i = 0; i < 8; i++) {
                    float4 qq = q4[i];
                    acc = fmaf(kr[i].x, qq.x, acc);
                    acc = fmaf(kr[i].y, qq.y, acc);
                    acc = fmaf(kr[i].z, qq.z, acc);
                    acc = fmaf(kr[i].w, qq.w, acc);
                }
                int m = mask[(p * NR + q) * NK + k];
                sm.Ss[q][k] = m ? NEGINF : acc;
            }
        }
    }
    __syncthreads();

    // softmax: warp w handles row q=w
    {
        float mx = NEGINF;
        for (int k = l; k < NK; k += 32) mx = fmaxf(mx, sm.Ss[w][k]);
        #pragma unroll
        for (int o = 16; o; o >>= 1) mx = fmaxf(mx, __shfl_xor_sync(~0u, mx, o));
        float sum = 0.f;
        for (int k = l; k < NK; k += 32) {
            float e = __expf(sm.Ss[w][k] - mx);
            sm.Ss[w][k] = e; sum += e;
        }
        #pragma unroll
        for (int o = 16; o; o >>= 1) sum += __shfl_xor_sync(~0u, sum, o);
        float inv = 1.f / sum;
        for (int k = l; k < NK; k += 32) sm.Ss[w][k] *= inv;
    }
    __syncthreads();

    // x[q][d] = sum_k S[q][k] * V[k][d] ; V streamed through shared in chunks.
    const float4* Vp4 = (const float4*)(V + (size_t)(a * NP + p) * NK * HD);
    int q = l >> 2, dq = l & 3;
    float acc8[8] = {};
    for (int c0 = 0; c0 < NK; c0 += 128) {
        int clen = min(128, NK - c0);
        for (int i = t; i < clen * 8; i += 256) sm.Vs[i] = Vp4[c0 * 8 + i];
        __syncthreads();
        for (int kk = w; kk < clen; kk += 8) {
            float sv = sm.Ss[q][c0 + kk];
            float4 v0 = sm.Vs[kk * 8 + dq * 2];
            float4 v1 = sm.Vs[kk * 8 + dq * 2 + 1];
            acc8[0] = fmaf(sv, v0.x, acc8[0]);
            acc8[1] = fmaf(sv, v0.y, acc8[1]);
            acc8[2] = fmaf(sv, v0.z, acc8[2]);
            acc8[3] = fmaf(sv, v0.w, acc8[3]);
            acc8[4] = fmaf(sv, v1.x, acc8[4]);
            acc8[5] = fmaf(sv, v1.y, acc8[5]);
            acc8[6] = fmaf(sv, v1.z, acc8[6]);
            acc8[7] = fmaf(sv, v1.w, acc8[7]);
        }
        __syncthreads();
    }
    #pragma unroll
    for (int i = 0; i < 8; i++) sm.hs_x[w][q][dq * 8 + i] = acc8[i];
    __syncthreads();
    {
        int q2 = t >> 5, d2 = t & 31;
        float s = 0.f;
        #pragma unroll
        for (int ww = 0; ww < 8; ww++) s += sm.hs_x[ww][q2][d2];
        g_xcat[(p * NR + q2) * H + a * HD + d2] = s;
    }
}

// =====================================================================
// Kernel 4: qm = x_cat @ nn_O   (512x256 @ 256x256)
// grid (4 col-tiles, 64 row-groups); block: 8 rows x 64 cols,
// 2 accumulators/thread per nnO load, unroll 8 for MLP.
// =====================================================================
__global__ __launch_bounds__(256)
void k_qm(const float* __restrict__ nnO)
{
    __shared__ float xs[8][256];
    const int c0 = blockIdx.x * 64;
    const int r0 = blockIdx.y * 8;
    const int t = threadIdx.x;
    for (int i = t; i < 8 * 256; i += 256)
        xs[i >> 8][i & 255] = g_xcat[(r0 + (i >> 8)) * 256 + (i & 255)];
    __syncthreads();
    const int c  = c0 + (t & 63);
    const int rg = t >> 6;                 // 0..3 -> rows rg*2, rg*2+1
    float a0 = 0.f, a1 = 0.f;
    #pragma unroll 8
    for (int k = 0; k < 256; k++) {
        float wv = nnO[k * 256 + c];
        a0 = fmaf(xs[rg * 2 + 0][k], wv, a0);
        a1 = fmaf(xs[rg * 2 + 1][k], wv, a1);
    }
    g_qm[(r0 + rg * 2 + 0) * 256 + c] = a0;
    g_qm[(r0 + rg * 2 + 1) * 256 + c] = a1;
}

// =====================================================================
// Kernel 5: logits. block = (p, ktile of 64). warp owns one k per iter.
// =====================================================================
__global__ __launch_bounds__(256)
void k_logit(const float* __restrict__ X, const float* __restrict__ varfeat,
             const float* __restrict__ nnA, const float* __restrict__ nnB,
             const float* __restrict__ nnW, const int* __restrict__ mask)
{
    __shared__ float qs[8][256];
    const int p = blockIdx.y, kt = blockIdx.x;
    const int t = threadIdx.x, w = t >> 5, l = t & 31;
    for (int i = t; i < 2048; i += 256) qs[i >> 8][i & 255] = g_qm[p * 2048 + i];

    float Ar[8][8], Wr[8], Br[8];
    #pragma unroll
    for (int i = 0; i < 8; i++) {
        int hh = l + 32 * i;
        Wr[i] = nnW[hh];
        Br[i] = nnB[hh];
        #pragma unroll
        for (int v = 0; v < 8; v++) Ar[v][i] = nnA[v * 256 + hh];
    }
    __syncthreads();

    for (int it = 0; it < 8; it++) {
        int k = kt * 64 + it * 8 + w;
        if (k >= NK) continue;
        float vv[8];
        #pragma unroll
        for (int v = 0; v < 8; v++) vv[v] = __ldg(&varfeat[(p * VD + v) * NK + k]);
        const float* Xp = X + ((size_t)p * NK + k) * H;
        float base[8];
        #pragma unroll
        for (int i = 0; i < 8; i++) {
            float b = Xp[l + 32 * i] + Br[i];
            #pragma unroll
            for (int v = 0; v < 8; v++) b = fmaf(vv[v], Ar[v][i], b);
            base[i] = b;
        }
        #pragma unroll
        for (int q = 0; q < 8; q++) {
            float acc = 0.f;
            #pragma unroll
            for (int i = 0; i < 8; i++) {
                float tt = tanha(base[i] + qs[q][l + 32 * i]);
                acc = fmaf(tt, Wr[i], acc);
            }
            #pragma unroll
            for (int o = 16; o; o >>= 1) acc += __shfl_xor_sync(~0u, acc, o);
            if (l == 0) {
                int m = mask[(p * NR + q) * NK + k];
                g_logit[(p * NR + q) * NK + k] = m ? NEGINF : acc;
            }
        }
    }
}

// =====================================================================
// Kernel 6: greedy choose + log_softmax at chosen index. block per row b.
// =====================================================================
__global__ __launch_bounds__(256)
void k_choose(float* __restrict__ out)
{
    __shared__ float ls[NK];
    __shared__ float rv[256];
    __shared__ int   ri[256];
    __shared__ float rs[256];
    const int b = blockIdx.x;
    const int t = threadIdx.x;

    float lm = NEGINF; int li = 0x7fffffff;
    for (int k = t; k < NK; k += 256) {
        float lg = g_logit[b * NK + k];
        float l  = (lg == NEGINF) ? NEGINF : tanhf(lg) * 10.0f;
        ls[k] = l;
        if (l > lm || (l == lm && k < li)) { lm = l; li = k; }
    }
    rv[t] = lm; ri[t] = li;
    __syncthreads();
    for (int s = 128; s; s >>= 1) {
        if (t < s) {
            float v2 = rv[t + s]; int i2 = ri[t + s];
            if (v2 > rv[t] || (v2 == rv[t] && i2 < ri[t])) { rv[t] = v2; ri[t] = i2; }
        }
        __syncthreads();
    }
    float maxv = rv[0]; int chosen = ri[0];

    float psum = 0.f;
    for (int k = t; k < NK; k += 256) psum += __expf(ls[k] - maxv);
    rs[t] = psum;
    __syncthreads();
    for (int s = 128; s; s >>= 1) {
        if (t < s) rs[t] += rs[t + s];
        __syncthreads();
    }
    if (t == 0) out[2 * BB * H + b] = ls[chosen] - maxv - __logf(rs[0]);
}

// =====================================================================
// launch
// =====================================================================
extern "C" void kernel_launch(void* const* d_in, const int* in_sizes, int n_in,
                              void* d_out, int out_size)
{
    const float* X       = (const float*)d_in[0];
    const float* K       = (const float*)d_in[1];
    const float* V       = (const float*)d_in[2];
    const float* query   = (const float*)d_in[3];
    const float* state1  = (const float*)d_in[4];
    const float* state2  = (const float*)d_in[5];
    const float* varfeat = (const float*)d_in[6];
    const int*   mask    = (const int*)  d_in[7];
    const float* nnQ     = (const float*)d_in[8];
    const float* nnO     = (const float*)d_in[9];
    const float* nnA     = (const float*)d_in[10];
    const float* nnB     = (const float*)d_in[11];
    const float* nnW     = (const float*)d_in[12];
    const float* Wih     = (const float*)d_in[13];
    const float* Whh     = (const float*)d_in[14];
    const float* bih     = (const float*)d_in[15];
    const float* bhh     = (const float*)d_in[16];
    float* out = (float*)d_out;

    k_gates <<<dim3(16, 8), 256>>>(query, state1, Wih, Whh, bih, bhh);
    k_act   <<<512, 256>>>(state2, out);
    k_attn  <<<dim3(NP, HEADS), 256>>>(K, V, nnQ, mask, out);
    k_qm    <<<dim3(4, 64), 256>>>(nnO);
    k_logit <<<dim3(8, NP), 256>>>(X, varfeat, nnA, nnB, nnW, mask);
    k_choose<<<BB, 256>>>(out);
}